// round 12
// baseline (speedup 1.0000x reference)
#include <cuda_runtime.h>
#include <cstdint>

typedef unsigned long long ull;

// ---------------------------------------------------------------------------
//   img      [64][3][416][416]
//   conv1    5x5 VALID -> relu -> pool2 -> [64][6][206][206] (stored 208x208 padded)
//   conv2    5x5 VALID -> relu -> pool2 -> [64][16][101][101]
//   fc1      [64][163216] -> relu -> [64][64] -> boxes [1024][4]
//   roipool  -> [1024][3][16][16] -> 4x4 conv -> relu -> fc2 -> [1024][64]
// ---------------------------------------------------------------------------

// padded 208x208; rows/cols 206..207 never written -> static zero-init
// provides the zero padding conv2's loads expect.
__device__ float g_pool1[64 * 6 * 208 * 208];
__device__ float g_pool2[64 * 16 * 101 * 101];
__device__ float g_fc1part[101 * 64 * 64];
__device__ float4 g_roi[1024];

// ---- packed fp32x2 helpers ------------------------------------------------
__device__ __forceinline__ ull fma2(ull a, ull b, ull c) {
    ull d;
    asm("fma.rn.f32x2 %0, %1, %2, %3;" : "=l"(d) : "l"(a), "l"(b), "l"(c));
    return d;
}
__device__ __forceinline__ ull dup2(float v) {
    ull d;
    asm("mov.b64 %0, {%1, %1};" : "=l"(d) : "f"(v));
    return d;
}
__device__ __forceinline__ float2 unpk(ull a) {
    float2 r;
    asm("mov.b64 {%0, %1}, %2;" : "=f"(r.x), "=f"(r.y) : "l"(a));
    return r;
}

// ---------------------------------------------------------------------------
// conv1 + relu + maxpool2.  (R7 version — measured best: 690us build)
// Block: pooled tile 16(rows) x 32(cols). 256 threads = 16x16; each thread
// computes 2 adjacent pooled outputs (2x4 conv patch) for all 6 oc.
// ---------------------------------------------------------------------------
__global__ __launch_bounds__(256) void conv1_kernel(
    const float* __restrict__ img, const float* __restrict__ w,
    const float* __restrict__ bias) {
    __shared__ float sin[3][36 * 69];
    __shared__ float2 swp[3 * 25 * 3];   // [(ic*25+k)*3 + p]
    __shared__ float sb[6];
    const int bz = blockIdx.z, by = blockIdx.y, bx = blockIdx.x;
    const int tid = threadIdx.x;

    if (tid < 225) {
        int p = tid % 3, ick = tid / 3;
        int ic = ick / 25, k = ick % 25;
        swp[tid] = make_float2(w[(2 * p) * 75 + ic * 25 + k],
                               w[(2 * p + 1) * 75 + ic * 25 + k]);
    }
    if (tid < 6) sb[tid] = bias[tid];

    const int iy0 = by * 32, ix0 = bx * 64;
    for (int e = tid; e < 1836; e += 256) {
        int ic = e / 612, rem = e % 612, r = rem / 17, c4 = rem % 17;
        int gy = iy0 + r, gx = ix0 + 4 * c4;
        float4 v;
        if (gy < 416 && gx <= 412) {
            v = *(const float4*)&img[((size_t)bz * 3 + ic) * 416 * 416 +
                                     gy * 416 + gx];
        } else {
            const float* src = img + ((size_t)bz * 3 + ic) * 416 * 416;
            v.x = (gy < 416 && gx < 416) ? src[gy * 416 + gx] : 0.f;
            v.y = (gy < 416 && gx + 1 < 416) ? src[gy * 416 + gx + 1] : 0.f;
            v.z = (gy < 416 && gx + 2 < 416) ? src[gy * 416 + gx + 2] : 0.f;
            v.w = (gy < 416 && gx + 3 < 416) ? src[gy * 416 + gx + 3] : 0.f;
        }
        float* dst = &sin[ic][r * 69 + 4 * c4];
        dst[0] = v.x; dst[1] = v.y; dst[2] = v.z; dst[3] = v.w;
    }
    __syncthreads();

    const int ty = tid >> 4, tx = tid & 15;
    ull acc[3][2][4];
#pragma unroll
    for (int p = 0; p < 3; p++)
#pragma unroll
        for (int r = 0; r < 2; r++)
#pragma unroll
            for (int c = 0; c < 4; c++) acc[p][r][c] = 0ull;

    for (int ic = 0; ic < 3; ic++) {
        const float* S = &sin[ic][(2 * ty) * 69 + 4 * tx];
        const ull* W = (const ull*)&swp[ic * 75];
        ull RA[8], RB[8];
#pragma unroll
        for (int c = 0; c < 8; c++) RA[c] = dup2(S[c]);
#pragma unroll
        for (int ky = 0; ky < 5; ky++) {
            const float* Srow = S + (ky + 1) * 69;
#pragma unroll
            for (int c = 0; c < 8; c++) RB[c] = dup2(Srow[c]);
#pragma unroll
            for (int kx = 0; kx < 5; kx++) {
#pragma unroll
                for (int p = 0; p < 3; p++) {
                    ull wv = W[(ky * 5 + kx) * 3 + p];
#pragma unroll
                    for (int c = 0; c < 4; c++) {
                        acc[p][0][c] = fma2(RA[kx + c], wv, acc[p][0][c]);
                        acc[p][1][c] = fma2(RB[kx + c], wv, acc[p][1][c]);
                    }
                }
            }
#pragma unroll
            for (int c = 0; c < 8; c++) RA[c] = RB[c];
        }
    }

    const int py = by * 16 + ty;
    if (py < 206) {
#pragma unroll
        for (int d = 0; d < 2; d++) {
            const int px = bx * 32 + 2 * tx + d;
            if (px < 206) {
#pragma unroll
                for (int p = 0; p < 3; p++) {
                    float2 a00 = unpk(acc[p][0][2 * d]);
                    float2 a01 = unpk(acc[p][0][2 * d + 1]);
                    float2 a10 = unpk(acc[p][1][2 * d]);
                    float2 a11 = unpk(acc[p][1][2 * d + 1]);
                    float vlo = fmaxf(fmaxf(a00.x, a01.x), fmaxf(a10.x, a11.x));
                    float vhi = fmaxf(fmaxf(a00.y, a01.y), fmaxf(a10.y, a11.y));
                    g_pool1[(((size_t)bz * 6 + 2 * p) * 208 + py) * 208 + px] =
                        fmaxf(vlo + sb[2 * p], 0.f);
                    g_pool1[(((size_t)bz * 6 + 2 * p + 1) * 208 + py) * 208 + px] =
                        fmaxf(vhi + sb[2 * p + 1], 0.f);
                }
            }
        }
    }
}

// ---------------------------------------------------------------------------
// conv2 + relu + maxpool2.  (R8 version — measured best: 690us build)
// ---------------------------------------------------------------------------
__global__ __launch_bounds__(256) void conv2_kernel(
    const float* __restrict__ w, const float* __restrict__ bias) {
    __shared__ float sin[6][36 * 21];
    __shared__ float2 swp[6 * 25 * 8];   // [(ic*25+k)*8 + p]
    __shared__ float sb[16];
    const int bz = blockIdx.z, by = blockIdx.y, bx = blockIdx.x;
    const int tid = threadIdx.x;

    for (int i = tid; i < 1200; i += 256) {
        int p = i % 8, ick = i / 8;
        int ic = ick / 25, k = ick % 25;
        swp[i] = make_float2(w[((2 * p) * 6 + ic) * 25 + k],
                             w[((2 * p + 1) * 6 + ic) * 25 + k]);
    }
    if (tid < 16) sb[tid] = bias[tid];

    const int iy0 = by * 32, ix0 = bx * 16;
    for (int e = tid; e < 1080; e += 256) {
        int ic = e / 180, rem = e % 180, r = rem / 5, c4 = rem % 5;
        int gy = iy0 + r, gx = ix0 + 4 * c4;
        const float* src = g_pool1 + ((size_t)bz * 6 + ic) * 208 * 208;
        float4 v;
        if (gy < 208 && gx <= 204) {
            v = *(const float4*)&src[gy * 208 + gx];
        } else {
            v.x = (gy < 208 && gx < 208) ? src[gy * 208 + gx] : 0.f;
            v.y = (gy < 208 && gx + 1 < 208) ? src[gy * 208 + gx + 1] : 0.f;
            v.z = (gy < 208 && gx + 2 < 208) ? src[gy * 208 + gx + 2] : 0.f;
            v.w = (gy < 208 && gx + 3 < 208) ? src[gy * 208 + gx + 3] : 0.f;
        }
        float* dst = &sin[ic][r * 21 + 4 * c4];
        dst[0] = v.x; dst[1] = v.y; dst[2] = v.z; dst[3] = v.w;
    }
    __syncthreads();

    const int o = tid >> 6;             // 0..3 -> oc base 4*o
    const int t = tid & 63;
    const int ty = t >> 2, tx = t & 3;
    ull acc[2][2][4];
#pragma unroll
    for (int p = 0; p < 2; p++)
#pragma unroll
        for (int r = 0; r < 2; r++)
#pragma unroll
            for (int c = 0; c < 4; c++) acc[p][r][c] = 0ull;

    for (int ic = 0; ic < 6; ic++) {
        const float* S = &sin[ic][(2 * ty) * 21 + 4 * tx];
        const ull* W = (const ull*)&swp[ic * 200 + 2 * o];
        ull RA[8], RB[8];
#pragma unroll
        for (int c = 0; c < 8; c++) RA[c] = dup2(S[c]);
#pragma unroll
        for (int ky = 0; ky < 5; ky++) {
            const float* Srow = S + (ky + 1) * 21;
#pragma unroll
            for (int c = 0; c < 8; c++) RB[c] = dup2(Srow[c]);
#pragma unroll
            for (int kx = 0; kx < 5; kx++) {
#pragma unroll
                for (int p = 0; p < 2; p++) {
                    ull wv = W[(ky * 5 + kx) * 8 + p];
#pragma unroll
                    for (int c = 0; c < 4; c++) {
                        acc[p][0][c] = fma2(RA[kx + c], wv, acc[p][0][c]);
                        acc[p][1][c] = fma2(RB[kx + c], wv, acc[p][1][c]);
                    }
                }
            }
#pragma unroll
            for (int c = 0; c < 8; c++) RA[c] = RB[c];
        }
    }

    const int py = by * 16 + ty;
    if (py < 101) {
#pragma unroll
        for (int d = 0; d < 2; d++) {
            const int px = bx * 8 + 2 * tx + d;
            if (px < 101) {
#pragma unroll
                for (int p = 0; p < 2; p++) {
                    const int oc = 4 * o + 2 * p;
                    float2 a00 = unpk(acc[p][0][2 * d]);
                    float2 a01 = unpk(acc[p][0][2 * d + 1]);
                    float2 a10 = unpk(acc[p][1][2 * d]);
                    float2 a11 = unpk(acc[p][1][2 * d + 1]);
                    float vlo = fmaxf(fmaxf(a00.x, a01.x), fmaxf(a10.x, a11.x));
                    float vhi = fmaxf(fmaxf(a00.y, a01.y), fmaxf(a10.y, a11.y));
                    g_pool2[(((size_t)bz * 16 + oc) * 101 + py) * 101 + px] =
                        fmaxf(vlo + sb[oc], 0.f);
                    g_pool2[(((size_t)bz * 16 + oc + 1) * 101 + py) * 101 + px] =
                        fmaxf(vhi + sb[oc + 1], 0.f);
                }
            }
        }
    }
}

// ---------------------------------------------------------------------------
// fc1 split-K, scalar compute. Wide 32-column stages: same accumulation
// order as 16-col steps (kk ascending) -> bit-identical results, but half
// the barriers and double the LDG batch per stage.
// ---------------------------------------------------------------------------
__global__ __launch_bounds__(256) void fc1_kernel(const float* __restrict__ w) {
    __shared__ float xs[64][33];
    __shared__ float ws[64][33];
    const int blk = blockIdx.x;
    const int tid = threadIdx.x;
    const int tb = tid >> 4, to = tid & 15;
    float acc[4][4];
#pragma unroll
    for (int i = 0; i < 4; i++)
#pragma unroll
        for (int j = 0; j < 4; j++) acc[i][j] = 0.f;

    const int k0 = blk * 1616;
    // 50 stages of 32 columns (steps 0..99)
    for (int st = 0; st < 50; st++) {
        const int kbase = k0 + st * 32;
#pragma unroll
        for (int i = 0; i < 8; i++) {
            int e = tid + i * 256;
            int row = e >> 5, col = e & 31;
            xs[row][col] = g_pool2[(size_t)row * 163216 + kbase + col];
            ws[row][col] = w[(size_t)row * 163216 + kbase + col];
        }
        __syncthreads();
#pragma unroll
        for (int kk = 0; kk < 32; kk++) {
            float xr[4], wr[4];
#pragma unroll
            for (int i = 0; i < 4; i++) xr[i] = xs[tb + 16 * i][kk];
#pragma unroll
            for (int j = 0; j < 4; j++) wr[j] = ws[to + 16 * j][kk];
#pragma unroll
            for (int i = 0; i < 4; i++)
#pragma unroll
                for (int j = 0; j < 4; j++)
                    acc[i][j] = fmaf(xr[i], wr[j], acc[i][j]);
        }
        __syncthreads();
    }
    // final 16-column stage (step 100)
    {
        const int kbase = k0 + 1600;
#pragma unroll
        for (int i = 0; i < 4; i++) {
            int e = tid + i * 256;
            int row = e >> 4, col = e & 15;
            xs[row][col] = g_pool2[(size_t)row * 163216 + kbase + col];
            ws[row][col] = w[(size_t)row * 163216 + kbase + col];
        }
        __syncthreads();
#pragma unroll
        for (int kk = 0; kk < 16; kk++) {
            float xr[4], wr[4];
#pragma unroll
            for (int i = 0; i < 4; i++) xr[i] = xs[tb + 16 * i][kk];
#pragma unroll
            for (int j = 0; j < 4; j++) wr[j] = ws[to + 16 * j][kk];
#pragma unroll
            for (int i = 0; i < 4; i++)
#pragma unroll
                for (int j = 0; j < 4; j++)
                    acc[i][j] = fmaf(xr[i], wr[j], acc[i][j]);
        }
    }

    float* outp = g_fc1part + (size_t)blk * 4096;
#pragma unroll
    for (int i = 0; i < 4; i++)
#pragma unroll
        for (int j = 0; j < 4; j++)
            outp[(tb + 16 * i) * 64 + (to + 16 * j)] = acc[i][j];
}

// ---------------------------------------------------------------------------
// fc1 finalize + box decode. 64 blocks, coalesced reduction over partials.
// ---------------------------------------------------------------------------
__global__ __launch_bounds__(256) void fc1_finalize_boxes(
    const float* __restrict__ fc1_b) {
    __shared__ float partial[4][64];
    __shared__ float xv[64];
    const int b = blockIdx.x;
    const int tid = threadIdx.x;
    const int j = tid & 63, ch = tid >> 6;
    float s = 0.f;
    for (int t = ch; t < 101; t += 4)
        s += g_fc1part[t * 4096 + b * 64 + j];
    partial[ch][j] = s;
    __syncthreads();
    if (tid < 64) {
        float v = partial[0][tid] + partial[1][tid] + partial[2][tid] +
                  partial[3][tid] + fc1_b[tid];
        xv[tid] = fmaxf(v, 0.f);
    }
    __syncthreads();
    if (tid < 16) {
        const int i = tid;
        float x1 = fminf(fmaxf(rintf(xv[i] * 0.5f), 0.f), 415.f);
        float y1 = fminf(fmaxf(rintf(xv[16 + i] * 0.5f), 0.f), 415.f);
        float x2 = fminf(fmaxf(rintf(xv[32 + i] * 0.5f), 0.f), 415.f);
        float y2 = fminf(fmaxf(rintf(xv[48 + i] * 0.5f), 0.f), 415.f);
        float bw = fmaxf(x2 - x1 + 1.f, 1.f) * (1.f / 16.f);
        float bh = fmaxf(y2 - y1 + 1.f, 1.f) * (1.f / 16.f);
        g_roi[b * 16 + i] = make_float4(x1, y1, bw, bh);
    }
}

// ---------------------------------------------------------------------------
// Fused RoIPool + 4x4 conv + fc2. One block per roi.  (naive — measured best)
// ---------------------------------------------------------------------------
__global__ __launch_bounds__(256) void roi_kernel(
    const float* __restrict__ img, const float* __restrict__ rw,
    const float* __restrict__ rb, const float* __restrict__ w2,
    const float* __restrict__ b2, float* __restrict__ out) {
    __shared__ float pooled[3][16][16];
    __shared__ float yv[169];
    __shared__ float swc[48];
    __shared__ float sbc;
    const int n = blockIdx.x, tid = threadIdx.x;

    if (tid < 48) swc[tid] = rw[tid];
    if (tid == 0) sbc = rb[0];

    const float4 p = g_roi[n];   // x1, y1, bw, bh
    const int b = n >> 4;
    const int ph = tid >> 4, pw = tid & 15;

    const int hs = (int)fminf(floorf((float)ph * p.w) + p.y, 416.f);
    const int he = (int)fminf(ceilf((float)(ph + 1) * p.w) + p.y, 416.f);
    const int wsb = (int)fminf(floorf((float)pw * p.z) + p.x, 416.f);
    const int web = (int)fminf(ceilf((float)(pw + 1) * p.z) + p.x, 416.f);

    float m0, m1, m2;
    if (he > hs && web > wsb) {
        m0 = m1 = m2 = -3.4e38f;
        const float* c0 = img + (size_t)b * 3 * 416 * 416;
        for (int yy = hs; yy < he; yy++) {
            const float* row = c0 + yy * 416;
            for (int xx = wsb; xx < web; xx++) {
                m0 = fmaxf(m0, row[xx]);
                m1 = fmaxf(m1, row[xx + 416 * 416]);
                m2 = fmaxf(m2, row[xx + 2 * 416 * 416]);
            }
        }
    } else {
        m0 = m1 = m2 = 0.f;
    }
    pooled[0][ph][pw] = m0;
    pooled[1][ph][pw] = m1;
    pooled[2][ph][pw] = m2;
    __syncthreads();

    if (tid < 169) {
        const int oy = tid / 13, ox = tid % 13;
        float s = sbc;
#pragma unroll
        for (int c = 0; c < 3; c++)
#pragma unroll
            for (int ky = 0; ky < 4; ky++)
#pragma unroll
                for (int kx = 0; kx < 4; kx++)
                    s = fmaf(pooled[c][oy + ky][ox + kx],
                             swc[(c * 4 + ky) * 4 + kx], s);
        yv[tid] = fmaxf(s, 0.f);
    }
    __syncthreads();

    if (tid < 64) {
        float s = b2[tid];
        const float* wr = w2 + tid * 169;
        for (int pp = 0; pp < 169; pp++) s = fmaf(yv[pp], __ldg(&wr[pp]), s);
        out[(size_t)n * 64 + tid] = fmaxf(s, 0.f);
    }
}

// ---------------------------------------------------------------------------
extern "C" void kernel_launch(void* const* d_in, const int* in_sizes, int n_in,
                              void* d_out, int out_size) {
    const float* img     = (const float*)d_in[0];
    const float* conv1_w = (const float*)d_in[1];
    const float* conv1_b = (const float*)d_in[2];
    const float* conv2_w = (const float*)d_in[3];
    const float* conv2_b = (const float*)d_in[4];
    const float* fc1_w   = (const float*)d_in[5];
    const float* fc1_b   = (const float*)d_in[6];
    const float* roi_w   = (const float*)d_in[7];
    const float* roi_b   = (const float*)d_in[8];
    const float* fc2_w   = (const float*)d_in[9];
    const float* fc2_b   = (const float*)d_in[10];
    float* out = (float*)d_out;

    dim3 g1(7, 13, 64);    // pooled 206: x 7*32=224, y 13*16=208
    conv1_kernel<<<g1, 256>>>(img, conv1_w, conv1_b);

    dim3 g2(13, 7, 64);    // pooled 101: x 13*8=104, y 7*16=112
    conv2_kernel<<<g2, 256>>>(conv2_w, conv2_b);

    fc1_kernel<<<101, 256>>>(fc1_w);
    fc1_finalize_boxes<<<64, 256>>>(fc1_b);
    roi_kernel<<<1024, 256>>>(img, roi_w, roi_b, fc2_w, fc2_b, out);
}

// round 13
// speedup vs baseline: 1.0861x; 1.0861x over previous
#include <cuda_runtime.h>
#include <cstdint>

typedef unsigned long long ull;

// ---------------------------------------------------------------------------
//   img      [64][3][416][416]
//   conv1    5x5 VALID -> relu -> pool2 -> [64][6][206][206] (stored 208x208 padded)
//   conv2    5x5 VALID -> relu -> pool2 -> [64][16][101][101]
//   fc1      [64][163216] -> relu -> [64][64] -> boxes [1024][4]
//   roipool  -> [1024][3][16][16] -> 4x4 conv -> relu -> fc2 -> [1024][64]
//
// This is byte-identical to the R8 build that measured 690.2us — submitted
// unchanged to test reproducibility of that number across container holds.
// ---------------------------------------------------------------------------

// padded 208x208; rows/cols 206..207 never written -> static zero-init
// provides the zero padding conv2's loads expect.
__device__ float g_pool1[64 * 6 * 208 * 208];
__device__ float g_pool2[64 * 16 * 101 * 101];
__device__ float g_fc1part[101 * 64 * 64];
__device__ float4 g_roi[1024];

// ---- packed fp32x2 helpers ------------------------------------------------
__device__ __forceinline__ ull fma2(ull a, ull b, ull c) {
    ull d;
    asm("fma.rn.f32x2 %0, %1, %2, %3;" : "=l"(d) : "l"(a), "l"(b), "l"(c));
    return d;
}
__device__ __forceinline__ ull dup2(float v) {
    ull d;
    asm("mov.b64 %0, {%1, %1};" : "=l"(d) : "f"(v));
    return d;
}
__device__ __forceinline__ float2 unpk(ull a) {
    float2 r;
    asm("mov.b64 {%0, %1}, %2;" : "=f"(r.x), "=f"(r.y) : "l"(a));
    return r;
}

// ---------------------------------------------------------------------------
// conv1 + relu + maxpool2.  (R7 version — part of the 690us build)
// Block: pooled tile 16(rows) x 32(cols). 256 threads = 16x16; each thread
// computes 2 adjacent pooled outputs (2x4 conv patch) for all 6 oc.
// ---------------------------------------------------------------------------
__global__ __launch_bounds__(256) void conv1_kernel(
    const float* __restrict__ img, const float* __restrict__ w,
    const float* __restrict__ bias) {
    __shared__ float sin[3][36 * 69];
    __shared__ float2 swp[3 * 25 * 3];   // [(ic*25+k)*3 + p]
    __shared__ float sb[6];
    const int bz = blockIdx.z, by = blockIdx.y, bx = blockIdx.x;
    const int tid = threadIdx.x;

    if (tid < 225) {
        int p = tid % 3, ick = tid / 3;
        int ic = ick / 25, k = ick % 25;
        swp[tid] = make_float2(w[(2 * p) * 75 + ic * 25 + k],
                               w[(2 * p + 1) * 75 + ic * 25 + k]);
    }
    if (tid < 6) sb[tid] = bias[tid];

    const int iy0 = by * 32, ix0 = bx * 64;
    for (int e = tid; e < 1836; e += 256) {
        int ic = e / 612, rem = e % 612, r = rem / 17, c4 = rem % 17;
        int gy = iy0 + r, gx = ix0 + 4 * c4;
        float4 v;
        if (gy < 416 && gx <= 412) {
            v = *(const float4*)&img[((size_t)bz * 3 + ic) * 416 * 416 +
                                     gy * 416 + gx];
        } else {
            const float* src = img + ((size_t)bz * 3 + ic) * 416 * 416;
            v.x = (gy < 416 && gx < 416) ? src[gy * 416 + gx] : 0.f;
            v.y = (gy < 416 && gx + 1 < 416) ? src[gy * 416 + gx + 1] : 0.f;
            v.z = (gy < 416 && gx + 2 < 416) ? src[gy * 416 + gx + 2] : 0.f;
            v.w = (gy < 416 && gx + 3 < 416) ? src[gy * 416 + gx + 3] : 0.f;
        }
        float* dst = &sin[ic][r * 69 + 4 * c4];
        dst[0] = v.x; dst[1] = v.y; dst[2] = v.z; dst[3] = v.w;
    }
    __syncthreads();

    const int ty = tid >> 4, tx = tid & 15;
    ull acc[3][2][4];
#pragma unroll
    for (int p = 0; p < 3; p++)
#pragma unroll
        for (int r = 0; r < 2; r++)
#pragma unroll
            for (int c = 0; c < 4; c++) acc[p][r][c] = 0ull;

    for (int ic = 0; ic < 3; ic++) {
        const float* S = &sin[ic][(2 * ty) * 69 + 4 * tx];
        const ull* W = (const ull*)&swp[ic * 75];
        ull RA[8], RB[8];
#pragma unroll
        for (int c = 0; c < 8; c++) RA[c] = dup2(S[c]);
#pragma unroll
        for (int ky = 0; ky < 5; ky++) {
            const float* Srow = S + (ky + 1) * 69;
#pragma unroll
            for (int c = 0; c < 8; c++) RB[c] = dup2(Srow[c]);
#pragma unroll
            for (int kx = 0; kx < 5; kx++) {
#pragma unroll
                for (int p = 0; p < 3; p++) {
                    ull wv = W[(ky * 5 + kx) * 3 + p];
#pragma unroll
                    for (int c = 0; c < 4; c++) {
                        acc[p][0][c] = fma2(RA[kx + c], wv, acc[p][0][c]);
                        acc[p][1][c] = fma2(RB[kx + c], wv, acc[p][1][c]);
                    }
                }
            }
#pragma unroll
            for (int c = 0; c < 8; c++) RA[c] = RB[c];
        }
    }

    const int py = by * 16 + ty;
    if (py < 206) {
#pragma unroll
        for (int d = 0; d < 2; d++) {
            const int px = bx * 32 + 2 * tx + d;
            if (px < 206) {
#pragma unroll
                for (int p = 0; p < 3; p++) {
                    float2 a00 = unpk(acc[p][0][2 * d]);
                    float2 a01 = unpk(acc[p][0][2 * d + 1]);
                    float2 a10 = unpk(acc[p][1][2 * d]);
                    float2 a11 = unpk(acc[p][1][2 * d + 1]);
                    float vlo = fmaxf(fmaxf(a00.x, a01.x), fmaxf(a10.x, a11.x));
                    float vhi = fmaxf(fmaxf(a00.y, a01.y), fmaxf(a10.y, a11.y));
                    g_pool1[(((size_t)bz * 6 + 2 * p) * 208 + py) * 208 + px] =
                        fmaxf(vlo + sb[2 * p], 0.f);
                    g_pool1[(((size_t)bz * 6 + 2 * p + 1) * 208 + py) * 208 + px] =
                        fmaxf(vhi + sb[2 * p + 1], 0.f);
                }
            }
        }
    }
}

// ---------------------------------------------------------------------------
// conv2 + relu + maxpool2.  (R8 version — part of the 690us build)
// ---------------------------------------------------------------------------
__global__ __launch_bounds__(256) void conv2_kernel(
    const float* __restrict__ w, const float* __restrict__ bias) {
    __shared__ float sin[6][36 * 21];
    __shared__ float2 swp[6 * 25 * 8];   // [(ic*25+k)*8 + p]
    __shared__ float sb[16];
    const int bz = blockIdx.z, by = blockIdx.y, bx = blockIdx.x;
    const int tid = threadIdx.x;

    for (int i = tid; i < 1200; i += 256) {
        int p = i % 8, ick = i / 8;
        int ic = ick / 25, k = ick % 25;
        swp[i] = make_float2(w[((2 * p) * 6 + ic) * 25 + k],
                             w[((2 * p + 1) * 6 + ic) * 25 + k]);
    }
    if (tid < 16) sb[tid] = bias[tid];

    const int iy0 = by * 32, ix0 = bx * 16;
    for (int e = tid; e < 1080; e += 256) {
        int ic = e / 180, rem = e % 180, r = rem / 5, c4 = rem % 5;
        int gy = iy0 + r, gx = ix0 + 4 * c4;
        const float* src = g_pool1 + ((size_t)bz * 6 + ic) * 208 * 208;
        float4 v;
        if (gy < 208 && gx <= 204) {
            v = *(const float4*)&src[gy * 208 + gx];
        } else {
            v.x = (gy < 208 && gx < 208) ? src[gy * 208 + gx] : 0.f;
            v.y = (gy < 208 && gx + 1 < 208) ? src[gy * 208 + gx + 1] : 0.f;
            v.z = (gy < 208 && gx + 2 < 208) ? src[gy * 208 + gx + 2] : 0.f;
            v.w = (gy < 208 && gx + 3 < 208) ? src[gy * 208 + gx + 3] : 0.f;
        }
        float* dst = &sin[ic][r * 21 + 4 * c4];
        dst[0] = v.x; dst[1] = v.y; dst[2] = v.z; dst[3] = v.w;
    }
    __syncthreads();

    const int o = tid >> 6;             // 0..3 -> oc base 4*o
    const int t = tid & 63;
    const int ty = t >> 2, tx = t & 3;
    ull acc[2][2][4];
#pragma unroll
    for (int p = 0; p < 2; p++)
#pragma unroll
        for (int r = 0; r < 2; r++)
#pragma unroll
            for (int c = 0; c < 4; c++) acc[p][r][c] = 0ull;

    for (int ic = 0; ic < 6; ic++) {
        const float* S = &sin[ic][(2 * ty) * 21 + 4 * tx];
        const ull* W = (const ull*)&swp[ic * 200 + 2 * o];
        ull RA[8], RB[8];
#pragma unroll
        for (int c = 0; c < 8; c++) RA[c] = dup2(S[c]);
#pragma unroll
        for (int ky = 0; ky < 5; ky++) {
            const float* Srow = S + (ky + 1) * 21;
#pragma unroll
            for (int c = 0; c < 8; c++) RB[c] = dup2(Srow[c]);
#pragma unroll
            for (int kx = 0; kx < 5; kx++) {
#pragma unroll
                for (int p = 0; p < 2; p++) {
                    ull wv = W[(ky * 5 + kx) * 8 + p];
#pragma unroll
                    for (int c = 0; c < 4; c++) {
                        acc[p][0][c] = fma2(RA[kx + c], wv, acc[p][0][c]);
                        acc[p][1][c] = fma2(RB[kx + c], wv, acc[p][1][c]);
                    }
                }
            }
#pragma unroll
            for (int c = 0; c < 8; c++) RA[c] = RB[c];
        }
    }

    const int py = by * 16 + ty;
    if (py < 101) {
#pragma unroll
        for (int d = 0; d < 2; d++) {
            const int px = bx * 8 + 2 * tx + d;
            if (px < 101) {
#pragma unroll
                for (int p = 0; p < 2; p++) {
                    const int oc = 4 * o + 2 * p;
                    float2 a00 = unpk(acc[p][0][2 * d]);
                    float2 a01 = unpk(acc[p][0][2 * d + 1]);
                    float2 a10 = unpk(acc[p][1][2 * d]);
                    float2 a11 = unpk(acc[p][1][2 * d + 1]);
                    float vlo = fmaxf(fmaxf(a00.x, a01.x), fmaxf(a10.x, a11.x));
                    float vhi = fmaxf(fmaxf(a00.y, a01.y), fmaxf(a10.y, a11.y));
                    g_pool2[(((size_t)bz * 16 + oc) * 101 + py) * 101 + px] =
                        fmaxf(vlo + sb[oc], 0.f);
                    g_pool2[(((size_t)bz * 16 + oc + 1) * 101 + py) * 101 + px] =
                        fmaxf(vhi + sb[oc + 1], 0.f);
                }
            }
        }
    }
}

// ---------------------------------------------------------------------------
// fc1 split-K (scalar 16-col version — part of the 690us build).
// ---------------------------------------------------------------------------
__global__ __launch_bounds__(256) void fc1_kernel(const float* __restrict__ w) {
    __shared__ float xs[64][17];
    __shared__ float ws[64][17];
    const int blk = blockIdx.x;
    const int tid = threadIdx.x;
    const int tb = tid >> 4, to = tid & 15;
    float acc[4][4];
#pragma unroll
    for (int i = 0; i < 4; i++)
#pragma unroll
        for (int j = 0; j < 4; j++) acc[i][j] = 0.f;

    const int k0 = blk * 1616;
    for (int s = 0; s < 101; s++) {
        const int kbase = k0 + s * 16;
#pragma unroll
        for (int i = 0; i < 4; i++) {
            int e = tid + i * 256;
            int row = e >> 4, col = e & 15;
            xs[row][col] = g_pool2[(size_t)row * 163216 + kbase + col];
            ws[row][col] = w[(size_t)row * 163216 + kbase + col];
        }
        __syncthreads();
#pragma unroll
        for (int kk = 0; kk < 16; kk++) {
            float xr[4], wr[4];
#pragma unroll
            for (int i = 0; i < 4; i++) xr[i] = xs[tb + 16 * i][kk];
#pragma unroll
            for (int j = 0; j < 4; j++) wr[j] = ws[to + 16 * j][kk];
#pragma unroll
            for (int i = 0; i < 4; i++)
#pragma unroll
                for (int j = 0; j < 4; j++)
                    acc[i][j] = fmaf(xr[i], wr[j], acc[i][j]);
        }
        __syncthreads();
    }

    float* outp = g_fc1part + (size_t)blk * 4096;
#pragma unroll
    for (int i = 0; i < 4; i++)
#pragma unroll
        for (int j = 0; j < 4; j++)
            outp[(tb + 16 * i) * 64 + (to + 16 * j)] = acc[i][j];
}

// ---------------------------------------------------------------------------
// fc1 finalize + box decode. 64 blocks, coalesced reduction over partials.
// ---------------------------------------------------------------------------
__global__ __launch_bounds__(256) void fc1_finalize_boxes(
    const float* __restrict__ fc1_b) {
    __shared__ float partial[4][64];
    __shared__ float xv[64];
    const int b = blockIdx.x;
    const int tid = threadIdx.x;
    const int j = tid & 63, ch = tid >> 6;
    float s = 0.f;
    for (int t = ch; t < 101; t += 4)
        s += g_fc1part[t * 4096 + b * 64 + j];
    partial[ch][j] = s;
    __syncthreads();
    if (tid < 64) {
        float v = partial[0][tid] + partial[1][tid] + partial[2][tid] +
                  partial[3][tid] + fc1_b[tid];
        xv[tid] = fmaxf(v, 0.f);
    }
    __syncthreads();
    if (tid < 16) {
        const int i = tid;
        float x1 = fminf(fmaxf(rintf(xv[i] * 0.5f), 0.f), 415.f);
        float y1 = fminf(fmaxf(rintf(xv[16 + i] * 0.5f), 0.f), 415.f);
        float x2 = fminf(fmaxf(rintf(xv[32 + i] * 0.5f), 0.f), 415.f);
        float y2 = fminf(fmaxf(rintf(xv[48 + i] * 0.5f), 0.f), 415.f);
        float bw = fmaxf(x2 - x1 + 1.f, 1.f) * (1.f / 16.f);
        float bh = fmaxf(y2 - y1 + 1.f, 1.f) * (1.f / 16.f);
        g_roi[b * 16 + i] = make_float4(x1, y1, bw, bh);
    }
}

// ---------------------------------------------------------------------------
// Fused RoIPool + 4x4 conv + fc2. One block per roi.  (naive — measured best)
// ---------------------------------------------------------------------------
__global__ __launch_bounds__(256) void roi_kernel(
    const float* __restrict__ img, const float* __restrict__ rw,
    const float* __restrict__ rb, const float* __restrict__ w2,
    const float* __restrict__ b2, float* __restrict__ out) {
    __shared__ float pooled[3][16][16];
    __shared__ float yv[169];
    __shared__ float swc[48];
    __shared__ float sbc;
    const int n = blockIdx.x, tid = threadIdx.x;

    if (tid < 48) swc[tid] = rw[tid];
    if (tid == 0) sbc = rb[0];

    const float4 p = g_roi[n];   // x1, y1, bw, bh
    const int b = n >> 4;
    const int ph = tid >> 4, pw = tid & 15;

    const int hs = (int)fminf(floorf((float)ph * p.w) + p.y, 416.f);
    const int he = (int)fminf(ceilf((float)(ph + 1) * p.w) + p.y, 416.f);
    const int wsb = (int)fminf(floorf((float)pw * p.z) + p.x, 416.f);
    const int web = (int)fminf(ceilf((float)(pw + 1) * p.z) + p.x, 416.f);

    float m0, m1, m2;
    if (he > hs && web > wsb) {
        m0 = m1 = m2 = -3.4e38f;
        const float* c0 = img + (size_t)b * 3 * 416 * 416;
        for (int yy = hs; yy < he; yy++) {
            const float* row = c0 + yy * 416;
            for (int xx = wsb; xx < web; xx++) {
                m0 = fmaxf(m0, row[xx]);
                m1 = fmaxf(m1, row[xx + 416 * 416]);
                m2 = fmaxf(m2, row[xx + 2 * 416 * 416]);
            }
        }
    } else {
        m0 = m1 = m2 = 0.f;
    }
    pooled[0][ph][pw] = m0;
    pooled[1][ph][pw] = m1;
    pooled[2][ph][pw] = m2;
    __syncthreads();

    if (tid < 169) {
        const int oy = tid / 13, ox = tid % 13;
        float s = sbc;
#pragma unroll
        for (int c = 0; c < 3; c++)
#pragma unroll
            for (int ky = 0; ky < 4; ky++)
#pragma unroll
                for (int kx = 0; kx < 4; kx++)
                    s = fmaf(pooled[c][oy + ky][ox + kx],
                             swc[(c * 4 + ky) * 4 + kx], s);
        yv[tid] = fmaxf(s, 0.f);
    }
    __syncthreads();

    if (tid < 64) {
        float s = b2[tid];
        const float* wr = w2 + tid * 169;
        for (int pp = 0; pp < 169; pp++) s = fmaf(yv[pp], __ldg(&wr[pp]), s);
        out[(size_t)n * 64 + tid] = fmaxf(s, 0.f);
    }
}

// ---------------------------------------------------------------------------
extern "C" void kernel_launch(void* const* d_in, const int* in_sizes, int n_in,
                              void* d_out, int out_size) {
    const float* img     = (const float*)d_in[0];
    const float* conv1_w = (const float*)d_in[1];
    const float* conv1_b = (const float*)d_in[2];
    const float* conv2_w = (const float*)d_in[3];
    const float* conv2_b = (const float*)d_in[4];
    const float* fc1_w   = (const float*)d_in[5];
    const float* fc1_b   = (const float*)d_in[6];
    const float* roi_w   = (const float*)d_in[7];
    const float* roi_b   = (const float*)d_in[8];
    const float* fc2_w   = (const float*)d_in[9];
    const float* fc2_b   = (const float*)d_in[10];
    float* out = (float*)d_out;

    dim3 g1(7, 13, 64);    // pooled 206: x 7*32=224, y 13*16=208
    conv1_kernel<<<g1, 256>>>(img, conv1_w, conv1_b);

    dim3 g2(13, 7, 64);    // pooled 101: x 13*8=104, y 7*16=112
    conv2_kernel<<<g2, 256>>>(conv2_w, conv2_b);

    fc1_kernel<<<101, 256>>>(fc1_w);
    fc1_finalize_boxes<<<64, 256>>>(fc1_b);
    roi_kernel<<<1024, 256>>>(img, roi_w, roi_b, fc2_w, fc2_b, out);
}

// round 14
// speedup vs baseline: 1.1025x; 1.0151x over previous
#include <cuda_runtime.h>
#include <cstdint>

typedef unsigned long long ull;

// ---------------------------------------------------------------------------
//   img      [64][3][416][416]
//   conv1    5x5 VALID -> relu -> pool2 -> [64][6][206][206] (stored 208x208 padded)
//   conv2    5x5 VALID -> relu -> pool2 -> [64][16][101][101]
//   fc1      [64][163216] -> relu -> [64][64] -> boxes [1024][4]
//   roipool  -> [1024][3][16][16] -> 4x4 conv -> relu -> fc2 -> [1024][64]
//
// Baseline: the verified-reproducible 690.2us build. Single change this round:
// roi_kernel window scan uses aligned float4 loads (same max over same values
// -> bit-identical output; ~2-4x fewer L2 sectors).
// ---------------------------------------------------------------------------

__device__ float g_pool1[64 * 6 * 208 * 208];
__device__ float g_pool2[64 * 16 * 101 * 101];
__device__ float g_fc1part[101 * 64 * 64];
__device__ float4 g_roi[1024];

// ---- packed fp32x2 helpers ------------------------------------------------
__device__ __forceinline__ ull fma2(ull a, ull b, ull c) {
    ull d;
    asm("fma.rn.f32x2 %0, %1, %2, %3;" : "=l"(d) : "l"(a), "l"(b), "l"(c));
    return d;
}
__device__ __forceinline__ ull dup2(float v) {
    ull d;
    asm("mov.b64 %0, {%1, %1};" : "=l"(d) : "f"(v));
    return d;
}
__device__ __forceinline__ float2 unpk(ull a) {
    float2 r;
    asm("mov.b64 {%0, %1}, %2;" : "=f"(r.x), "=f"(r.y) : "l"(a));
    return r;
}

// ---------------------------------------------------------------------------
// conv1 + relu + maxpool2.  (R7 version — part of the 690us build)
// ---------------------------------------------------------------------------
__global__ __launch_bounds__(256) void conv1_kernel(
    const float* __restrict__ img, const float* __restrict__ w,
    const float* __restrict__ bias) {
    __shared__ float sin[3][36 * 69];
    __shared__ float2 swp[3 * 25 * 3];   // [(ic*25+k)*3 + p]
    __shared__ float sb[6];
    const int bz = blockIdx.z, by = blockIdx.y, bx = blockIdx.x;
    const int tid = threadIdx.x;

    if (tid < 225) {
        int p = tid % 3, ick = tid / 3;
        int ic = ick / 25, k = ick % 25;
        swp[tid] = make_float2(w[(2 * p) * 75 + ic * 25 + k],
                               w[(2 * p + 1) * 75 + ic * 25 + k]);
    }
    if (tid < 6) sb[tid] = bias[tid];

    const int iy0 = by * 32, ix0 = bx * 64;
    for (int e = tid; e < 1836; e += 256) {
        int ic = e / 612, rem = e % 612, r = rem / 17, c4 = rem % 17;
        int gy = iy0 + r, gx = ix0 + 4 * c4;
        float4 v;
        if (gy < 416 && gx <= 412) {
            v = *(const float4*)&img[((size_t)bz * 3 + ic) * 416 * 416 +
                                     gy * 416 + gx];
        } else {
            const float* src = img + ((size_t)bz * 3 + ic) * 416 * 416;
            v.x = (gy < 416 && gx < 416) ? src[gy * 416 + gx] : 0.f;
            v.y = (gy < 416 && gx + 1 < 416) ? src[gy * 416 + gx + 1] : 0.f;
            v.z = (gy < 416 && gx + 2 < 416) ? src[gy * 416 + gx + 2] : 0.f;
            v.w = (gy < 416 && gx + 3 < 416) ? src[gy * 416 + gx + 3] : 0.f;
        }
        float* dst = &sin[ic][r * 69 + 4 * c4];
        dst[0] = v.x; dst[1] = v.y; dst[2] = v.z; dst[3] = v.w;
    }
    __syncthreads();

    const int ty = tid >> 4, tx = tid & 15;
    ull acc[3][2][4];
#pragma unroll
    for (int p = 0; p < 3; p++)
#pragma unroll
        for (int r = 0; r < 2; r++)
#pragma unroll
            for (int c = 0; c < 4; c++) acc[p][r][c] = 0ull;

    for (int ic = 0; ic < 3; ic++) {
        const float* S = &sin[ic][(2 * ty) * 69 + 4 * tx];
        const ull* W = (const ull*)&swp[ic * 75];
        ull RA[8], RB[8];
#pragma unroll
        for (int c = 0; c < 8; c++) RA[c] = dup2(S[c]);
#pragma unroll
        for (int ky = 0; ky < 5; ky++) {
            const float* Srow = S + (ky + 1) * 69;
#pragma unroll
            for (int c = 0; c < 8; c++) RB[c] = dup2(Srow[c]);
#pragma unroll
            for (int kx = 0; kx < 5; kx++) {
#pragma unroll
                for (int p = 0; p < 3; p++) {
                    ull wv = W[(ky * 5 + kx) * 3 + p];
#pragma unroll
                    for (int c = 0; c < 4; c++) {
                        acc[p][0][c] = fma2(RA[kx + c], wv, acc[p][0][c]);
                        acc[p][1][c] = fma2(RB[kx + c], wv, acc[p][1][c]);
                    }
                }
            }
#pragma unroll
            for (int c = 0; c < 8; c++) RA[c] = RB[c];
        }
    }

    const int py = by * 16 + ty;
    if (py < 206) {
#pragma unroll
        for (int d = 0; d < 2; d++) {
            const int px = bx * 32 + 2 * tx + d;
            if (px < 206) {
#pragma unroll
                for (int p = 0; p < 3; p++) {
                    float2 a00 = unpk(acc[p][0][2 * d]);
                    float2 a01 = unpk(acc[p][0][2 * d + 1]);
                    float2 a10 = unpk(acc[p][1][2 * d]);
                    float2 a11 = unpk(acc[p][1][2 * d + 1]);
                    float vlo = fmaxf(fmaxf(a00.x, a01.x), fmaxf(a10.x, a11.x));
                    float vhi = fmaxf(fmaxf(a00.y, a01.y), fmaxf(a10.y, a11.y));
                    g_pool1[(((size_t)bz * 6 + 2 * p) * 208 + py) * 208 + px] =
                        fmaxf(vlo + sb[2 * p], 0.f);
                    g_pool1[(((size_t)bz * 6 + 2 * p + 1) * 208 + py) * 208 + px] =
                        fmaxf(vhi + sb[2 * p + 1], 0.f);
                }
            }
        }
    }
}

// ---------------------------------------------------------------------------
// conv2 + relu + maxpool2.  (R8 version — part of the 690us build)
// ---------------------------------------------------------------------------
__global__ __launch_bounds__(256) void conv2_kernel(
    const float* __restrict__ w, const float* __restrict__ bias) {
    __shared__ float sin[6][36 * 21];
    __shared__ float2 swp[6 * 25 * 8];   // [(ic*25+k)*8 + p]
    __shared__ float sb[16];
    const int bz = blockIdx.z, by = blockIdx.y, bx = blockIdx.x;
    const int tid = threadIdx.x;

    for (int i = tid; i < 1200; i += 256) {
        int p = i % 8, ick = i / 8;
        int ic = ick / 25, k = ick % 25;
        swp[i] = make_float2(w[((2 * p) * 6 + ic) * 25 + k],
                             w[((2 * p + 1) * 6 + ic) * 25 + k]);
    }
    if (tid < 16) sb[tid] = bias[tid];

    const int iy0 = by * 32, ix0 = bx * 16;
    for (int e = tid; e < 1080; e += 256) {
        int ic = e / 180, rem = e % 180, r = rem / 5, c4 = rem % 5;
        int gy = iy0 + r, gx = ix0 + 4 * c4;
        const float* src = g_pool1 + ((size_t)bz * 6 + ic) * 208 * 208;
        float4 v;
        if (gy < 208 && gx <= 204) {
            v = *(const float4*)&src[gy * 208 + gx];
        } else {
            v.x = (gy < 208 && gx < 208) ? src[gy * 208 + gx] : 0.f;
            v.y = (gy < 208 && gx + 1 < 208) ? src[gy * 208 + gx + 1] : 0.f;
            v.z = (gy < 208 && gx + 2 < 208) ? src[gy * 208 + gx + 2] : 0.f;
            v.w = (gy < 208 && gx + 3 < 208) ? src[gy * 208 + gx + 3] : 0.f;
        }
        float* dst = &sin[ic][r * 21 + 4 * c4];
        dst[0] = v.x; dst[1] = v.y; dst[2] = v.z; dst[3] = v.w;
    }
    __syncthreads();

    const int o = tid >> 6;             // 0..3 -> oc base 4*o
    const int t = tid & 63;
    const int ty = t >> 2, tx = t & 3;
    ull acc[2][2][4];
#pragma unroll
    for (int p = 0; p < 2; p++)
#pragma unroll
        for (int r = 0; r < 2; r++)
#pragma unroll
            for (int c = 0; c < 4; c++) acc[p][r][c] = 0ull;

    for (int ic = 0; ic < 6; ic++) {
        const float* S = &sin[ic][(2 * ty) * 21 + 4 * tx];
        const ull* W = (const ull*)&swp[ic * 200 + 2 * o];
        ull RA[8], RB[8];
#pragma unroll
        for (int c = 0; c < 8; c++) RA[c] = dup2(S[c]);
#pragma unroll
        for (int ky = 0; ky < 5; ky++) {
            const float* Srow = S + (ky + 1) * 21;
#pragma unroll
            for (int c = 0; c < 8; c++) RB[c] = dup2(Srow[c]);
#pragma unroll
            for (int kx = 0; kx < 5; kx++) {
#pragma unroll
                for (int p = 0; p < 2; p++) {
                    ull wv = W[(ky * 5 + kx) * 8 + p];
#pragma unroll
                    for (int c = 0; c < 4; c++) {
                        acc[p][0][c] = fma2(RA[kx + c], wv, acc[p][0][c]);
                        acc[p][1][c] = fma2(RB[kx + c], wv, acc[p][1][c]);
                    }
                }
            }
#pragma unroll
            for (int c = 0; c < 8; c++) RA[c] = RB[c];
        }
    }

    const int py = by * 16 + ty;
    if (py < 101) {
#pragma unroll
        for (int d = 0; d < 2; d++) {
            const int px = bx * 8 + 2 * tx + d;
            if (px < 101) {
#pragma unroll
                for (int p = 0; p < 2; p++) {
                    const int oc = 4 * o + 2 * p;
                    float2 a00 = unpk(acc[p][0][2 * d]);
                    float2 a01 = unpk(acc[p][0][2 * d + 1]);
                    float2 a10 = unpk(acc[p][1][2 * d]);
                    float2 a11 = unpk(acc[p][1][2 * d + 1]);
                    float vlo = fmaxf(fmaxf(a00.x, a01.x), fmaxf(a10.x, a11.x));
                    float vhi = fmaxf(fmaxf(a00.y, a01.y), fmaxf(a10.y, a11.y));
                    g_pool2[(((size_t)bz * 16 + oc) * 101 + py) * 101 + px] =
                        fmaxf(vlo + sb[oc], 0.f);
                    g_pool2[(((size_t)bz * 16 + oc + 1) * 101 + py) * 101 + px] =
                        fmaxf(vhi + sb[oc + 1], 0.f);
                }
            }
        }
    }
}

// ---------------------------------------------------------------------------
// fc1 split-K (scalar 16-col version — part of the 690us build).
// ---------------------------------------------------------------------------
__global__ __launch_bounds__(256) void fc1_kernel(const float* __restrict__ w) {
    __shared__ float xs[64][17];
    __shared__ float ws[64][17];
    const int blk = blockIdx.x;
    const int tid = threadIdx.x;
    const int tb = tid >> 4, to = tid & 15;
    float acc[4][4];
#pragma unroll
    for (int i = 0; i < 4; i++)
#pragma unroll
        for (int j = 0; j < 4; j++) acc[i][j] = 0.f;

    const int k0 = blk * 1616;
    for (int s = 0; s < 101; s++) {
        const int kbase = k0 + s * 16;
#pragma unroll
        for (int i = 0; i < 4; i++) {
            int e = tid + i * 256;
            int row = e >> 4, col = e & 15;
            xs[row][col] = g_pool2[(size_t)row * 163216 + kbase + col];
            ws[row][col] = w[(size_t)row * 163216 + kbase + col];
        }
        __syncthreads();
#pragma unroll
        for (int kk = 0; kk < 16; kk++) {
            float xr[4], wr[4];
#pragma unroll
            for (int i = 0; i < 4; i++) xr[i] = xs[tb + 16 * i][kk];
#pragma unroll
            for (int j = 0; j < 4; j++) wr[j] = ws[to + 16 * j][kk];
#pragma unroll
            for (int i = 0; i < 4; i++)
#pragma unroll
                for (int j = 0; j < 4; j++)
                    acc[i][j] = fmaf(xr[i], wr[j], acc[i][j]);
        }
        __syncthreads();
    }

    float* outp = g_fc1part + (size_t)blk * 4096;
#pragma unroll
    for (int i = 0; i < 4; i++)
#pragma unroll
        for (int j = 0; j < 4; j++)
            outp[(tb + 16 * i) * 64 + (to + 16 * j)] = acc[i][j];
}

// ---------------------------------------------------------------------------
// fc1 finalize + box decode. 64 blocks, coalesced reduction over partials.
// ---------------------------------------------------------------------------
__global__ __launch_bounds__(256) void fc1_finalize_boxes(
    const float* __restrict__ fc1_b) {
    __shared__ float partial[4][64];
    __shared__ float xv[64];
    const int b = blockIdx.x;
    const int tid = threadIdx.x;
    const int j = tid & 63, ch = tid >> 6;
    float s = 0.f;
    for (int t = ch; t < 101; t += 4)
        s += g_fc1part[t * 4096 + b * 64 + j];
    partial[ch][j] = s;
    __syncthreads();
    if (tid < 64) {
        float v = partial[0][tid] + partial[1][tid] + partial[2][tid] +
                  partial[3][tid] + fc1_b[tid];
        xv[tid] = fmaxf(v, 0.f);
    }
    __syncthreads();
    if (tid < 16) {
        const int i = tid;
        float x1 = fminf(fmaxf(rintf(xv[i] * 0.5f), 0.f), 415.f);
        float y1 = fminf(fmaxf(rintf(xv[16 + i] * 0.5f), 0.f), 415.f);
        float x2 = fminf(fmaxf(rintf(xv[32 + i] * 0.5f), 0.f), 415.f);
        float y2 = fminf(fmaxf(rintf(xv[48 + i] * 0.5f), 0.f), 415.f);
        float bw = fmaxf(x2 - x1 + 1.f, 1.f) * (1.f / 16.f);
        float bh = fmaxf(y2 - y1 + 1.f, 1.f) * (1.f / 16.f);
        g_roi[b * 16 + i] = make_float4(x1, y1, bw, bh);
    }
}

// ---------------------------------------------------------------------------
// Fused RoIPool + 4x4 conv + fc2. One block per roi. Same naive per-bin scan
// as the 690us build, but window rows are read with aligned float4 chunks
// (img rows are 16B-aligned at x%4==0). Max over the same value set ->
// bit-identical results; ~2-4x fewer L2 sectors.
// ---------------------------------------------------------------------------
__global__ __launch_bounds__(256) void roi_kernel(
    const float* __restrict__ img, const float* __restrict__ rw,
    const float* __restrict__ rb, const float* __restrict__ w2,
    const float* __restrict__ b2, float* __restrict__ out) {
    __shared__ float pooled[3][16][16];
    __shared__ float yv[169];
    __shared__ float swc[48];
    __shared__ float sbc;
    const int n = blockIdx.x, tid = threadIdx.x;

    if (tid < 48) swc[tid] = rw[tid];
    if (tid == 0) sbc = rb[0];

    const float4 p = g_roi[n];   // x1, y1, bw, bh
    const int b = n >> 4;
    const int ph = tid >> 4, pw = tid & 15;

    const int hs = (int)fminf(floorf((float)ph * p.w) + p.y, 416.f);
    const int he = (int)fminf(ceilf((float)(ph + 1) * p.w) + p.y, 416.f);
    const int wsb = (int)fminf(floorf((float)pw * p.z) + p.x, 416.f);
    const int web = (int)fminf(ceilf((float)(pw + 1) * p.z) + p.x, 416.f);

    float m0, m1, m2;
    if (he > hs && web > wsb) {
        m0 = m1 = m2 = -3.4e38f;
        const float* c0 = img + (size_t)b * 3 * 416 * 416;
        const int astart0 = (wsb + 3) & ~3;   // first 16B-aligned x
        const int aend0 = web & ~3;           // end of aligned region
        for (int yy = hs; yy < he; yy++) {
            const float* r0 = c0 + yy * 416;
            const float* r1 = r0 + 416 * 416;
            const float* r2 = r0 + 2 * 416 * 416;
            if (astart0 < aend0) {
                for (int xx = wsb; xx < astart0; xx++) {
                    m0 = fmaxf(m0, r0[xx]);
                    m1 = fmaxf(m1, r1[xx]);
                    m2 = fmaxf(m2, r2[xx]);
                }
                for (int xx = astart0; xx < aend0; xx += 4) {
                    float4 v0 = *(const float4*)&r0[xx];
                    float4 v1 = *(const float4*)&r1[xx];
                    float4 v2 = *(const float4*)&r2[xx];
                    m0 = fmaxf(m0, fmaxf(fmaxf(v0.x, v0.y), fmaxf(v0.z, v0.w)));
                    m1 = fmaxf(m1, fmaxf(fmaxf(v1.x, v1.y), fmaxf(v1.z, v1.w)));
                    m2 = fmaxf(m2, fmaxf(fmaxf(v2.x, v2.y), fmaxf(v2.z, v2.w)));
                }
                for (int xx = aend0; xx < web; xx++) {
                    m0 = fmaxf(m0, r0[xx]);
                    m1 = fmaxf(m1, r1[xx]);
                    m2 = fmaxf(m2, r2[xx]);
                }
            } else {
                for (int xx = wsb; xx < web; xx++) {
                    m0 = fmaxf(m0, r0[xx]);
                    m1 = fmaxf(m1, r1[xx]);
                    m2 = fmaxf(m2, r2[xx]);
                }
            }
        }
    } else {
        m0 = m1 = m2 = 0.f;
    }
    pooled[0][ph][pw] = m0;
    pooled[1][ph][pw] = m1;
    pooled[2][ph][pw] = m2;
    __syncthreads();

    if (tid < 169) {
        const int oy = tid / 13, ox = tid % 13;
        float s = sbc;
#pragma unroll
        for (int c = 0; c < 3; c++)
#pragma unroll
            for (int ky = 0; ky < 4; ky++)
#pragma unroll
                for (int kx = 0; kx < 4; kx++)
                    s = fmaf(pooled[c][oy + ky][ox + kx],
                             swc[(c * 4 + ky) * 4 + kx], s);
        yv[tid] = fmaxf(s, 0.f);
    }
    __syncthreads();

    if (tid < 64) {
        float s = b2[tid];
        const float* wr = w2 + tid * 169;
        for (int pp = 0; pp < 169; pp++) s = fmaf(yv[pp], __ldg(&wr[pp]), s);
        out[(size_t)n * 64 + tid] = fmaxf(s, 0.f);
    }
}

// ---------------------------------------------------------------------------
extern "C" void kernel_launch(void* const* d_in, const int* in_sizes, int n_in,
                              void* d_out, int out_size) {
    const float* img     = (const float*)d_in[0];
    const float* conv1_w = (const float*)d_in[1];
    const float* conv1_b = (const float*)d_in[2];
    const float* conv2_w = (const float*)d_in[3];
    const float* conv2_b = (const float*)d_in[4];
    const float* fc1_w   = (const float*)d_in[5];
    const float* fc1_b   = (const float*)d_in[6];
    const float* roi_w   = (const float*)d_in[7];
    const float* roi_b   = (const float*)d_in[8];
    const float* fc2_w   = (const float*)d_in[9];
    const float* fc2_b   = (const float*)d_in[10];
    float* out = (float*)d_out;

    dim3 g1(7, 13, 64);    // pooled 206: x 7*32=224, y 13*16=208
    conv1_kernel<<<g1, 256>>>(img, conv1_w, conv1_b);

    dim3 g2(13, 7, 64);    // pooled 101: x 13*8=104, y 7*16=112
    conv2_kernel<<<g2, 256>>>(conv2_w, conv2_b);

    fc1_kernel<<<101, 256>>>(fc1_w);
    fc1_finalize_boxes<<<64, 256>>>(fc1_b);
    roi_kernel<<<1024, 256>>>(img, roi_w, roi_b, fc2_w, fc2_b, out);
}